// round 2
// baseline (speedup 1.0000x reference)
#include <cuda_runtime.h>
#include <cuda_bf16.h>

#define NROWS   8192
#define BATCH   8
#define DIM     256
#define MAXDEG  128
#define NWORDS  (NROWS * NROWS / 32)   // 2,097,152 words = 8 MB

// ---------------- device scratch (static; no allocations allowed) ----------
__device__ __align__(16) unsigned g_bitmap[NWORDS];
__device__ int   g_deg[NROWS];
__device__ int   g_cols[NROWS * MAXDEG];
__device__ __align__(16) float g_y[BATCH * NROWS * DIM];   // 64 MB intermediate x@W
__device__ int   g_edges_are_i32;   // 1 if edges buffer is int32, 0 if int64

// ---------------- f32x2 packed-FMA helpers ---------------------------------
__device__ __forceinline__ unsigned long long f32x2_dup(float x) {
    unsigned long long r;
    asm("mov.b64 %0, {%1, %1};" : "=l"(r) : "f"(x));
    return r;
}
__device__ __forceinline__ void fma_f32x2(unsigned long long& d,
                                          unsigned long long a,
                                          unsigned long long b) {
    asm("fma.rn.f32x2 %0, %1, %2, %0;" : "+l"(d) : "l"(a), "l"(b));
}
__device__ __forceinline__ float f32x2_lo(unsigned long long v) {
    return __uint_as_float((unsigned)(v & 0xffffffffull));
}
__device__ __forceinline__ float f32x2_hi(unsigned long long v) {
    return __uint_as_float((unsigned)(v >> 32));
}

// ---------------- kernel 1: clear bitmap + flag ------------------------------
__global__ void k_clear() {
    int i = blockIdx.x * 256 + threadIdx.x;          // 2048 * 256 = 524288 uint4
    reinterpret_cast<uint4*>(g_bitmap)[i] = make_uint4(0u, 0u, 0u, 0u);
    if (i == 0) g_edges_are_i32 = 0;
}

// ---------------- kernel 1b: detect edge dtype --------------------------------
// If the buffer holds int64 indices (< 8192), every odd 32-bit word is zero.
// If it holds int32 pairs, odd words are random dst indices — virtually
// guaranteed nonzero somewhere in the first 4096 words. Deterministic.
__global__ void k_detect(const int* __restrict__ ew) {
    int j = threadIdx.x;                 // 0..255, single block
    int found = 0;
#pragma unroll
    for (int r = 0; r < 8; r++) {
        int idx = 2 * (j * 8 + r) + 1;   // odd words among first 4096
        if (ew[idx] != 0) found = 1;
    }
    if (found) atomicOr(&g_edges_are_i32, 1);
}

// ---------------- kernel 2: scatter edges into bitmap (dedup) ---------------
__global__ void k_scatter(const void* __restrict__ edges, int ne) {
    int i = blockIdx.x * blockDim.x + threadIdx.x;
    if (i >= ne) return;
    unsigned s, t;
    if (g_edges_are_i32) {
        const int* e = (const int*)edges;
        s = (unsigned)e[2 * i];
        t = (unsigned)e[2 * i + 1];
    } else {
        const long long* e = (const long long*)edges;
        s = (unsigned)e[2 * i];
        t = (unsigned)e[2 * i + 1];
    }
    unsigned idx = s * (unsigned)NROWS + t;
    atomicOr(&g_bitmap[idx >> 5], 1u << (idx & 31u));
}

// ---------------- kernel 3: bitmap -> sorted CSR (1 warp / row) -------------
__global__ void k_csr() {
    int gwarp = (blockIdx.x * blockDim.x + threadIdx.x) >> 5;
    int lane  = threadIdx.x & 31;
    if (gwarp >= NROWS) return;
    const unsigned* w = g_bitmap + gwarp * (NROWS / 32);   // 256 words
    int* cols = g_cols + gwarp * MAXDEG;
    int total = 0;
#pragma unroll
    for (int c = 0; c < 8; c++) {
        unsigned word = w[c * 32 + lane];
        int cnt = __popc(word);
        int inc = cnt;
#pragma unroll
        for (int off = 1; off < 32; off <<= 1) {
            int v = __shfl_up_sync(0xffffffffu, inc, off);
            if (lane >= off) inc += v;
        }
        int base = total + (inc - cnt);
        int colbase = (c * 32 + lane) * 32;
        while (word) {
            int b = __ffs(word) - 1;
            word &= word - 1;
            if (base < MAXDEG) cols[base] = colbase + b;
            base++;
        }
        total += __shfl_sync(0xffffffffu, inc, 31);
    }
    if (lane == 0) g_deg[gwarp] = total < MAXDEG ? total : MAXDEG;
}

// ---------------- kernel 4: y = x @ W  (fp32, f32x2-packed SGEMM) -----------
// BM=128, BN=128, BK=16, 256 threads, 8x8 per thread (as 4 row-pairs x 8 cols)
__global__ void __launch_bounds__(256) k_gemm(const float* __restrict__ X,
                                              const float* __restrict__ W,
                                              float* __restrict__ Y) {
    __shared__ __align__(16) float As[16][128];   // As[k][m]
    __shared__ __align__(16) float Bs[16][128];   // Bs[k][n]

    const int bm  = blockIdx.y * 128;
    const int bn  = blockIdx.x * 128;
    const int tid = threadIdx.x;
    const int tm  = tid >> 4;    // 0..15
    const int tn  = tid & 15;    // 0..15

    unsigned long long acc[4][8];
#pragma unroll
    for (int i = 0; i < 4; i++)
#pragma unroll
        for (int j = 0; j < 8; j++) acc[i][j] = 0ull;

    for (int kt = 0; kt < DIM; kt += 16) {
#pragma unroll
        for (int l = 0; l < 2; l++) {
            int idx = tid + l * 256;           // 0..511
            int row = idx >> 2, c4 = idx & 3;
            float4 v = *reinterpret_cast<const float4*>(
                &X[(size_t)(bm + row) * DIM + kt + c4 * 4]);
            As[c4 * 4 + 0][row] = v.x;
            As[c4 * 4 + 1][row] = v.y;
            As[c4 * 4 + 2][row] = v.z;
            As[c4 * 4 + 3][row] = v.w;
        }
#pragma unroll
        for (int l = 0; l < 2; l++) {
            int idx = tid + l * 256;           // 0..511
            int row = idx >> 5, c = idx & 31;
            *reinterpret_cast<float4*>(&Bs[row][c * 4]) =
                *reinterpret_cast<const float4*>(&W[(kt + row) * DIM + bn + c * 4]);
        }
        __syncthreads();

#pragma unroll
        for (int k = 0; k < 16; k++) {
            ulonglong2 a01 = *reinterpret_cast<const ulonglong2*>(&As[k][tm * 8]);
            ulonglong2 a23 = *reinterpret_cast<const ulonglong2*>(&As[k][tm * 8 + 4]);
            unsigned long long ap[4] = {a01.x, a01.y, a23.x, a23.y};
            float4 b0 = *reinterpret_cast<const float4*>(&Bs[k][tn * 8]);
            float4 b1 = *reinterpret_cast<const float4*>(&Bs[k][tn * 8 + 4]);
            unsigned long long bd[8];
            bd[0] = f32x2_dup(b0.x); bd[1] = f32x2_dup(b0.y);
            bd[2] = f32x2_dup(b0.z); bd[3] = f32x2_dup(b0.w);
            bd[4] = f32x2_dup(b1.x); bd[5] = f32x2_dup(b1.y);
            bd[6] = f32x2_dup(b1.z); bd[7] = f32x2_dup(b1.w);
#pragma unroll
            for (int i = 0; i < 4; i++)
#pragma unroll
                for (int j = 0; j < 8; j++)
                    fma_f32x2(acc[i][j], ap[i], bd[j]);
        }
        __syncthreads();
    }

#pragma unroll
    for (int i = 0; i < 4; i++) {
        size_t r = bm + tm * 8 + 2 * i;
        float* p0 = &Y[r * DIM + bn + tn * 8];
        float4 w0 = make_float4(f32x2_lo(acc[i][0]), f32x2_lo(acc[i][1]),
                                f32x2_lo(acc[i][2]), f32x2_lo(acc[i][3]));
        float4 w1 = make_float4(f32x2_lo(acc[i][4]), f32x2_lo(acc[i][5]),
                                f32x2_lo(acc[i][6]), f32x2_lo(acc[i][7]));
        float4 w2 = make_float4(f32x2_hi(acc[i][0]), f32x2_hi(acc[i][1]),
                                f32x2_hi(acc[i][2]), f32x2_hi(acc[i][3]));
        float4 w3 = make_float4(f32x2_hi(acc[i][4]), f32x2_hi(acc[i][5]),
                                f32x2_hi(acc[i][6]), f32x2_hi(acc[i][7]));
        *reinterpret_cast<float4*>(p0)           = w0;
        *reinterpret_cast<float4*>(p0 + 4)       = w1;
        *reinterpret_cast<float4*>(p0 + DIM)     = w2;
        *reinterpret_cast<float4*>(p0 + DIM + 4) = w3;
    }
}

// ---------------- kernel 5: h = A@y, LeakyReLU, LayerNorm (fused) -----------
__global__ void __launch_bounds__(256) k_spmm_ln(const float* __restrict__ Y,
                                                 const float* __restrict__ gamma,
                                                 const float* __restrict__ beta,
                                                 float* __restrict__ out) {
    const int n   = blockIdx.x;
    const int b   = blockIdx.y;
    const int tid = threadIdx.x;

    __shared__ int   cols_s[MAXDEG];
    __shared__ float ss[8], qq[8];

    const int deg = g_deg[n];
    if (tid < MAXDEG && tid < deg) cols_s[tid] = g_cols[n * MAXDEG + tid];
    __syncthreads();

    const float* Yb = Y + (size_t)b * NROWS * DIM;
    float a0 = 0.f, a1 = 0.f, a2 = 0.f, a3 = 0.f;
    int i = 0;
    for (; i + 4 <= deg; i += 4) {
        a0 += __ldg(&Yb[(size_t)cols_s[i]     * DIM + tid]);
        a1 += __ldg(&Yb[(size_t)cols_s[i + 1] * DIM + tid]);
        a2 += __ldg(&Yb[(size_t)cols_s[i + 2] * DIM + tid]);
        a3 += __ldg(&Yb[(size_t)cols_s[i + 3] * DIM + tid]);
    }
    for (; i < deg; i++) a0 += __ldg(&Yb[(size_t)cols_s[i] * DIM + tid]);
    float v = (a0 + a1) + (a2 + a3);

    v = v >= 0.f ? v : 0.1f * v;   // LeakyReLU(0.1)

    float s = v, q = v * v;
#pragma unroll
    for (int off = 16; off > 0; off >>= 1) {
        s += __shfl_down_sync(0xffffffffu, s, off);
        q += __shfl_down_sync(0xffffffffu, q, off);
    }
    int warp = tid >> 5, lane = tid & 31;
    if (lane == 0) { ss[warp] = s; qq[warp] = q; }
    __syncthreads();
    if (warp == 0) {
        s = lane < 8 ? ss[lane] : 0.f;
        q = lane < 8 ? qq[lane] : 0.f;
#pragma unroll
        for (int off = 4; off > 0; off >>= 1) {
            s += __shfl_down_sync(0xffffffffu, s, off);
            q += __shfl_down_sync(0xffffffffu, q, off);
        }
        if (lane == 0) { ss[0] = s; qq[0] = q; }
    }
    __syncthreads();

    const float mean = ss[0] * (1.f / 256.f);
    const float var  = qq[0] * (1.f / 256.f) - mean * mean;
    const float inv  = rsqrtf(var + 1e-5f);
    out[((size_t)b * NROWS + n) * DIM + tid] =
        gamma[tid] * (v - mean) * inv + beta[tid];
}

// ---------------- launcher ---------------------------------------------------
extern "C" void kernel_launch(void* const* d_in, const int* in_sizes, int n_in,
                              void* d_out, int out_size) {
    const float* x     = (const float*)d_in[0];   // (8, 8192, 256) f32
    const float* W     = (const float*)d_in[1];   // (256, 256) f32
    const float* gamma = (const float*)d_in[2];   // (256,) f32
    const float* beta  = (const float*)d_in[3];   // (256,) f32
    const void*  edges = d_in[4];                 // (262144, 2) int32 or int64
    const int ne = in_sizes[4] / 2;               // 262144 pairs either way
    float* out = (float*)d_out;

    // 1. clear adjacency bitmap (8 MB) + reset dtype flag
    k_clear<<<2048, 256>>>();
    // 1b. detect int32 vs int64 edge layout (reads first 4096 words only)
    k_detect<<<1, 256>>>((const int*)edges);
    // 2. scatter edges (deduplicating via bitmap)
    k_scatter<<<(ne + 255) / 256, 256>>>(edges, ne);
    // 3. bitmap -> sorted per-row column lists (deterministic)
    k_csr<<<NROWS / 8, 256>>>();
    // 4. y = x @ W   (fp32, f32x2 packed FMA)
    dim3 ggrid(DIM / 128, (BATCH * NROWS) / 128);     // (2, 512)
    k_gemm<<<ggrid, 256>>>(x, W, g_y);
    // 5. h = A @ y, LeakyReLU, LayerNorm — fused, h never hits DRAM
    dim3 sgrid(NROWS, BATCH);
    k_spmm_ln<<<sgrid, 256>>>(g_y, gamma, beta, out);
}

// round 3
// speedup vs baseline: 1.0817x; 1.0817x over previous
#include <cuda_runtime.h>
#include <cuda_bf16.h>

#define NROWS   8192
#define BATCH   8
#define DIM     256
#define MAXDEG  128
#define NWORDS  (NROWS * NROWS / 32)   // 2,097,152 words = 8 MB

// ---------------- device scratch (static; no allocations allowed) ----------
__device__ __align__(16) unsigned g_bitmap[NWORDS];
__device__ int   g_deg[NROWS];
__device__ int   g_cols[NROWS * MAXDEG];
__device__ __align__(16) float g_y[BATCH * NROWS * DIM];   // 64 MB intermediate x@W
__device__ int   g_edges_are_i32;   // 1 if edges buffer is int32, 0 if int64

// ---------------- f32x2 packed-FMA helpers ---------------------------------
__device__ __forceinline__ unsigned long long f32x2_dup(float x) {
    unsigned long long r;
    asm("mov.b64 %0, {%1, %1};" : "=l"(r) : "f"(x));
    return r;
}
__device__ __forceinline__ void fma_f32x2(unsigned long long& d,
                                          unsigned long long a,
                                          unsigned long long b) {
    asm("fma.rn.f32x2 %0, %1, %2, %0;" : "+l"(d) : "l"(a), "l"(b));
}
__device__ __forceinline__ float f32x2_lo(unsigned long long v) {
    return __uint_as_float((unsigned)(v & 0xffffffffull));
}
__device__ __forceinline__ float f32x2_hi(unsigned long long v) {
    return __uint_as_float((unsigned)(v >> 32));
}

// ---------------- kernel 1: clear bitmap + flag ------------------------------
__global__ void k_clear() {
    int i = blockIdx.x * 256 + threadIdx.x;          // 2048 * 256 = 524288 uint4
    reinterpret_cast<uint4*>(g_bitmap)[i] = make_uint4(0u, 0u, 0u, 0u);
    if (i == 0) g_edges_are_i32 = 0;
}

// ---------------- kernel 1b: detect edge dtype -------------------------------
// int64 indices < 8192 -> every odd 32-bit word is zero. int32 pairs -> odd
// words are random dst indices, virtually guaranteed nonzero. Deterministic.
__global__ void k_detect(const int* __restrict__ ew) {
    int j = threadIdx.x;                 // 0..255, single block
    int found = 0;
#pragma unroll
    for (int r = 0; r < 8; r++) {
        int idx = 2 * (j * 8 + r) + 1;   // odd words among first 4096
        if (ew[idx] != 0) found = 1;
    }
    if (found) atomicOr(&g_edges_are_i32, 1);
}

// ---------------- kernel 2: scatter edges into bitmap (dedup) ---------------
__global__ void k_scatter(const void* __restrict__ edges, int ne) {
    int i = blockIdx.x * blockDim.x + threadIdx.x;
    if (i >= ne) return;
    unsigned s, t;
    if (g_edges_are_i32) {
        const int* e = (const int*)edges;
        s = (unsigned)e[2 * i];
        t = (unsigned)e[2 * i + 1];
    } else {
        const long long* e = (const long long*)edges;
        s = (unsigned)e[2 * i];
        t = (unsigned)e[2 * i + 1];
    }
    unsigned idx = s * (unsigned)NROWS + t;
    atomicOr(&g_bitmap[idx >> 5], 1u << (idx & 31u));
}

// ---------------- kernel 3: bitmap -> sorted CSR (1 warp / row) -------------
__global__ void k_csr() {
    int gwarp = (blockIdx.x * blockDim.x + threadIdx.x) >> 5;
    int lane  = threadIdx.x & 31;
    if (gwarp >= NROWS) return;
    const unsigned* w = g_bitmap + gwarp * (NROWS / 32);   // 256 words
    int* cols = g_cols + gwarp * MAXDEG;
    int total = 0;
#pragma unroll
    for (int c = 0; c < 8; c++) {
        unsigned word = w[c * 32 + lane];
        int cnt = __popc(word);
        int inc = cnt;
#pragma unroll
        for (int off = 1; off < 32; off <<= 1) {
            int v = __shfl_up_sync(0xffffffffu, inc, off);
            if (lane >= off) inc += v;
        }
        int base = total + (inc - cnt);
        int colbase = (c * 32 + lane) * 32;
        while (word) {
            int b = __ffs(word) - 1;
            word &= word - 1;
            if (base < MAXDEG) cols[base] = colbase + b;
            base++;
        }
        total += __shfl_sync(0xffffffffu, inc, 31);
    }
    if (lane == 0) g_deg[gwarp] = total < MAXDEG ? total : MAXDEG;
}

// ---------------- kernel 4: y = x @ W  (fp32, f32x2-packed SGEMM) -----------
// BM=128, BN=128, BK=16, 256 threads, 8x8 per thread (as 4 row-pairs x 8 cols)
__global__ void __launch_bounds__(256) k_gemm(const float* __restrict__ X,
                                              const float* __restrict__ W,
                                              float* __restrict__ Y) {
    __shared__ __align__(16) float As[16][128];   // As[k][m]
    __shared__ __align__(16) float Bs[16][128];   // Bs[k][n]

    const int bm  = blockIdx.y * 128;
    const int bn  = blockIdx.x * 128;
    const int tid = threadIdx.x;
    const int tm  = tid >> 4;    // 0..15
    const int tn  = tid & 15;    // 0..15

    unsigned long long acc[4][8];
#pragma unroll
    for (int i = 0; i < 4; i++)
#pragma unroll
        for (int j = 0; j < 8; j++) acc[i][j] = 0ull;

    for (int kt = 0; kt < DIM; kt += 16) {
#pragma unroll
        for (int l = 0; l < 2; l++) {
            int idx = tid + l * 256;           // 0..511
            int row = idx >> 2, c4 = idx & 3;
            float4 v = *reinterpret_cast<const float4*>(
                &X[(size_t)(bm + row) * DIM + kt + c4 * 4]);
            As[c4 * 4 + 0][row] = v.x;
            As[c4 * 4 + 1][row] = v.y;
            As[c4 * 4 + 2][row] = v.z;
            As[c4 * 4 + 3][row] = v.w;
        }
#pragma unroll
        for (int l = 0; l < 2; l++) {
            int idx = tid + l * 256;           // 0..511
            int row = idx >> 5, c = idx & 31;
            *reinterpret_cast<float4*>(&Bs[row][c * 4]) =
                *reinterpret_cast<const float4*>(&W[(kt + row) * DIM + bn + c * 4]);
        }
        __syncthreads();

#pragma unroll
        for (int k = 0; k < 16; k++) {
            ulonglong2 a01 = *reinterpret_cast<const ulonglong2*>(&As[k][tm * 8]);
            ulonglong2 a23 = *reinterpret_cast<const ulonglong2*>(&As[k][tm * 8 + 4]);
            unsigned long long ap[4] = {a01.x, a01.y, a23.x, a23.y};
            float4 b0 = *reinterpret_cast<const float4*>(&Bs[k][tn * 8]);
            float4 b1 = *reinterpret_cast<const float4*>(&Bs[k][tn * 8 + 4]);
            unsigned long long bd[8];
            bd[0] = f32x2_dup(b0.x); bd[1] = f32x2_dup(b0.y);
            bd[2] = f32x2_dup(b0.z); bd[3] = f32x2_dup(b0.w);
            bd[4] = f32x2_dup(b1.x); bd[5] = f32x2_dup(b1.y);
            bd[6] = f32x2_dup(b1.z); bd[7] = f32x2_dup(b1.w);
#pragma unroll
            for (int i = 0; i < 4; i++)
#pragma unroll
                for (int j = 0; j < 8; j++)
                    fma_f32x2(acc[i][j], ap[i], bd[j]);
        }
        __syncthreads();
    }

#pragma unroll
    for (int i = 0; i < 4; i++) {
        size_t r = bm + tm * 8 + 2 * i;
        float* p0 = &Y[r * DIM + bn + tn * 8];
        float4 w0 = make_float4(f32x2_lo(acc[i][0]), f32x2_lo(acc[i][1]),
                                f32x2_lo(acc[i][2]), f32x2_lo(acc[i][3]));
        float4 w1 = make_float4(f32x2_lo(acc[i][4]), f32x2_lo(acc[i][5]),
                                f32x2_lo(acc[i][6]), f32x2_lo(acc[i][7]));
        float4 w2 = make_float4(f32x2_hi(acc[i][0]), f32x2_hi(acc[i][1]),
                                f32x2_hi(acc[i][2]), f32x2_hi(acc[i][3]));
        float4 w3 = make_float4(f32x2_hi(acc[i][4]), f32x2_hi(acc[i][5]),
                                f32x2_hi(acc[i][6]), f32x2_hi(acc[i][7]));
        *reinterpret_cast<float4*>(p0)           = w0;
        *reinterpret_cast<float4*>(p0 + 4)       = w1;
        *reinterpret_cast<float4*>(p0 + DIM)     = w2;
        *reinterpret_cast<float4*>(p0 + DIM + 4) = w3;
    }
}

// ---------------- kernel 5: h = A@y, LeakyReLU, LayerNorm (fused) -----------
// One block per node row n; 512 threads cover all 8 batches.
// Thread t: batch b = t>>6, float4 channel chunk c = t&63 (covers 256 floats).
// Column list loaded once per block (shared across the 8 batches).
__global__ void __launch_bounds__(512) k_spmm_ln(const float* __restrict__ Y,
                                                 const float* __restrict__ gamma,
                                                 const float* __restrict__ beta,
                                                 float* __restrict__ out) {
    const int n    = blockIdx.x;
    const int tid  = threadIdx.x;
    const int b    = tid >> 6;        // 0..7
    const int c    = tid & 63;        // 0..63 -> floats [c*4, c*4+4)
    const int warp = tid >> 5;        // 0..15 ; batch b owns warps 2b, 2b+1
    const int lane = tid & 31;

    __shared__ int   cols_s[MAXDEG];
    __shared__ float red_s[16], red_q[16];

    const int deg = g_deg[n];
    if (tid < deg) cols_s[tid] = g_cols[n * MAXDEG + tid];
    const float4 g4 = __ldg(&reinterpret_cast<const float4*>(gamma)[c]);
    const float4 be4 = __ldg(&reinterpret_cast<const float4*>(beta)[c]);
    __syncthreads();

    const float4* Yb4 =
        reinterpret_cast<const float4*>(Y + (size_t)b * NROWS * DIM);

    float4 a0 = make_float4(0.f, 0.f, 0.f, 0.f);
    float4 a1 = make_float4(0.f, 0.f, 0.f, 0.f);
    float4 a2 = make_float4(0.f, 0.f, 0.f, 0.f);
    float4 a3 = make_float4(0.f, 0.f, 0.f, 0.f);
    int i = 0;
    for (; i + 4 <= deg; i += 4) {
        float4 v0 = __ldg(&Yb4[(size_t)cols_s[i]     * 64 + c]);
        float4 v1 = __ldg(&Yb4[(size_t)cols_s[i + 1] * 64 + c]);
        float4 v2 = __ldg(&Yb4[(size_t)cols_s[i + 2] * 64 + c]);
        float4 v3 = __ldg(&Yb4[(size_t)cols_s[i + 3] * 64 + c]);
        a0.x += v0.x; a0.y += v0.y; a0.z += v0.z; a0.w += v0.w;
        a1.x += v1.x; a1.y += v1.y; a1.z += v1.z; a1.w += v1.w;
        a2.x += v2.x; a2.y += v2.y; a2.z += v2.z; a2.w += v2.w;
        a3.x += v3.x; a3.y += v3.y; a3.z += v3.z; a3.w += v3.w;
    }
    for (; i < deg; i++) {
        float4 v0 = __ldg(&Yb4[(size_t)cols_s[i] * 64 + c]);
        a0.x += v0.x; a0.y += v0.y; a0.z += v0.z; a0.w += v0.w;
    }
    float4 v;
    v.x = (a0.x + a1.x) + (a2.x + a3.x);
    v.y = (a0.y + a1.y) + (a2.y + a3.y);
    v.z = (a0.z + a1.z) + (a2.z + a3.z);
    v.w = (a0.w + a1.w) + (a2.w + a3.w);

    // LeakyReLU(0.1)
    v.x = v.x >= 0.f ? v.x : 0.1f * v.x;
    v.y = v.y >= 0.f ? v.y : 0.1f * v.y;
    v.z = v.z >= 0.f ? v.z : 0.1f * v.z;
    v.w = v.w >= 0.f ? v.w : 0.1f * v.w;

    // LayerNorm over the 256 channels of (b, n): reduce over 64 threads (2 warps)
    float s = (v.x + v.y) + (v.z + v.w);
    float q = (v.x * v.x + v.y * v.y) + (v.z * v.z + v.w * v.w);
#pragma unroll
    for (int off = 16; off > 0; off >>= 1) {
        s += __shfl_down_sync(0xffffffffu, s, off);
        q += __shfl_down_sync(0xffffffffu, q, off);
    }
    if (lane == 0) { red_s[warp] = s; red_q[warp] = q; }
    __syncthreads();
    const float st = red_s[2 * b] + red_s[2 * b + 1];
    const float qt = red_q[2 * b] + red_q[2 * b + 1];

    const float mean = st * (1.f / 256.f);
    const float var  = qt * (1.f / 256.f) - mean * mean;
    const float inv  = rsqrtf(var + 1e-5f);

    float4 o;
    o.x = g4.x * (v.x - mean) * inv + be4.x;
    o.y = g4.y * (v.y - mean) * inv + be4.y;
    o.z = g4.z * (v.z - mean) * inv + be4.z;
    o.w = g4.w * (v.w - mean) * inv + be4.w;
    reinterpret_cast<float4*>(out)[((size_t)b * NROWS + n) * 64 + c] = o;
}

// ---------------- launcher ---------------------------------------------------
extern "C" void kernel_launch(void* const* d_in, const int* in_sizes, int n_in,
                              void* d_out, int out_size) {
    const float* x     = (const float*)d_in[0];   // (8, 8192, 256) f32
    const float* W     = (const float*)d_in[1];   // (256, 256) f32
    const float* gamma = (const float*)d_in[2];   // (256,) f32
    const float* beta  = (const float*)d_in[3];   // (256,) f32
    const void*  edges = d_in[4];                 // (262144, 2) int32 or int64
    const int ne = in_sizes[4] / 2;               // 262144 pairs either way
    float* out = (float*)d_out;

    k_clear<<<2048, 256>>>();
    k_detect<<<1, 256>>>((const int*)edges);
    k_scatter<<<(ne + 255) / 256, 256>>>(edges, ne);
    k_csr<<<NROWS / 8, 256>>>();
    dim3 ggrid(DIM / 128, (BATCH * NROWS) / 128);     // (2, 512)
    k_gemm<<<ggrid, 256>>>(x, W, g_y);
    k_spmm_ln<<<NROWS, 512>>>(g_y, gamma, beta, out);
}

// round 4
// speedup vs baseline: 1.0823x; 1.0006x over previous
#include <cuda_runtime.h>
#include <cuda_bf16.h>

#define NROWS   8192
#define BATCH   8
#define DIM     256
#define MAXDEG  128
#define NWORDS  (NROWS * NROWS / 32)   // 2,097,152 words = 8 MB

// ---------------- device scratch (static; no allocations allowed) ----------
__device__ __align__(16) unsigned g_bitmap[NWORDS];
__device__ int   g_deg[NROWS];
__device__ int   g_cols[NROWS * MAXDEG];
__device__ __align__(16) float g_y[BATCH * NROWS * DIM];   // 64 MB intermediate x@W
__device__ int   g_edges_are_i32;   // 1 if edges buffer is int32, 0 if int64

// ---------------- kernel 1: clear bitmap + flag ------------------------------
__global__ void k_clear() {
    int i = blockIdx.x * 256 + threadIdx.x;          // 2048 * 256 = 524288 uint4
    reinterpret_cast<uint4*>(g_bitmap)[i] = make_uint4(0u, 0u, 0u, 0u);
    if (i == 0) g_edges_are_i32 = 0;
}

// ---------------- kernel 1b: detect edge dtype -------------------------------
// int64 indices < 8192 -> every odd 32-bit word is zero. int32 pairs -> odd
// words are random dst indices, virtually guaranteed nonzero. Deterministic.
__global__ void k_detect(const int* __restrict__ ew) {
    int j = threadIdx.x;                 // 0..255, single block
    int found = 0;
#pragma unroll
    for (int r = 0; r < 8; r++) {
        int idx = 2 * (j * 8 + r) + 1;   // odd words among first 4096
        if (ew[idx] != 0) found = 1;
    }
    if (found) atomicOr(&g_edges_are_i32, 1);
}

// ---------------- kernel 2: scatter edges into bitmap (dedup) ---------------
__global__ void k_scatter(const void* __restrict__ edges, int ne) {
    int i = blockIdx.x * blockDim.x + threadIdx.x;
    if (i >= ne) return;
    unsigned s, t;
    if (g_edges_are_i32) {
        const int* e = (const int*)edges;
        s = (unsigned)e[2 * i];
        t = (unsigned)e[2 * i + 1];
    } else {
        const long long* e = (const long long*)edges;
        s = (unsigned)e[2 * i];
        t = (unsigned)e[2 * i + 1];
    }
    unsigned idx = s * (unsigned)NROWS + t;
    atomicOr(&g_bitmap[idx >> 5], 1u << (idx & 31u));
}

// ---------------- kernel 3: bitmap -> sorted CSR (1 warp / row) -------------
__global__ void k_csr() {
    int gwarp = (blockIdx.x * blockDim.x + threadIdx.x) >> 5;
    int lane  = threadIdx.x & 31;
    if (gwarp >= NROWS) return;
    const unsigned* w = g_bitmap + gwarp * (NROWS / 32);   // 256 words
    int* cols = g_cols + gwarp * MAXDEG;
    int total = 0;
#pragma unroll
    for (int c = 0; c < 8; c++) {
        unsigned word = w[c * 32 + lane];
        int cnt = __popc(word);
        int inc = cnt;
#pragma unroll
        for (int off = 1; off < 32; off <<= 1) {
            int v = __shfl_up_sync(0xffffffffu, inc, off);
            if (lane >= off) inc += v;
        }
        int base = total + (inc - cnt);
        int colbase = (c * 32 + lane) * 32;
        while (word) {
            int b = __ffs(word) - 1;
            word &= word - 1;
            if (base < MAXDEG) cols[base] = colbase + b;
            base++;
        }
        total += __shfl_sync(0xffffffffu, inc, 31);
    }
    if (lane == 0) g_deg[gwarp] = total < MAXDEG ? total : MAXDEG;
}

// ---------------- kernel 4: y = x @ W  (canonical fp32 SGEMM) ---------------
// BM=128, BN=128, BK=8, 256 threads, 8x8 register tile per thread.
__global__ void __launch_bounds__(256, 2) k_gemm(const float* __restrict__ X,
                                                 const float* __restrict__ W,
                                                 float* __restrict__ Y) {
    __shared__ __align__(16) float As[8][128];    // As[k][m]  (X tile, transposed)
    __shared__ __align__(16) float Bs[8][128];    // Bs[k][n]  (W tile)

    const int bm  = blockIdx.y * 128;
    const int bn  = blockIdx.x * 128;
    const int tid = threadIdx.x;
    const int ty  = tid >> 4;    // 0..15 -> rows ty*8 .. ty*8+7
    const int tx  = tid & 15;    // 0..15 -> cols tx*8 .. tx*8+7

    // load indices
    const int lrow  = tid >> 1;          // 0..127  (X tile row)
    const int lc4   = (tid & 1) * 4;     // 0 or 4  (X tile col group)
    const int wrow  = tid >> 5;          // 0..7    (W tile row)
    const int wcol  = (tid & 31) * 4;    // 0..124  (W tile col group)

    float acc[8][8];
#pragma unroll
    for (int i = 0; i < 8; i++)
#pragma unroll
        for (int j = 0; j < 8; j++) acc[i][j] = 0.f;

    for (int kt = 0; kt < DIM; kt += 8) {
        // X tile: 128 rows x 8 cols -> As[k][m] (transposed store)
        float4 xv = *reinterpret_cast<const float4*>(
            &X[(size_t)(bm + lrow) * DIM + kt + lc4]);
        As[lc4 + 0][lrow] = xv.x;
        As[lc4 + 1][lrow] = xv.y;
        As[lc4 + 2][lrow] = xv.z;
        As[lc4 + 3][lrow] = xv.w;
        // W tile: 8 rows x 128 cols -> Bs[k][n]
        *reinterpret_cast<float4*>(&Bs[wrow][wcol]) =
            *reinterpret_cast<const float4*>(&W[(size_t)(kt + wrow) * DIM + bn + wcol]);
        __syncthreads();

#pragma unroll
        for (int k = 0; k < 8; k++) {
            float a[8], b[8];
            *reinterpret_cast<float4*>(&a[0]) =
                *reinterpret_cast<const float4*>(&As[k][ty * 8]);
            *reinterpret_cast<float4*>(&a[4]) =
                *reinterpret_cast<const float4*>(&As[k][ty * 8 + 4]);
            *reinterpret_cast<float4*>(&b[0]) =
                *reinterpret_cast<const float4*>(&Bs[k][tx * 8]);
            *reinterpret_cast<float4*>(&b[4]) =
                *reinterpret_cast<const float4*>(&Bs[k][tx * 8 + 4]);
#pragma unroll
            for (int i = 0; i < 8; i++)
#pragma unroll
                for (int j = 0; j < 8; j++)
                    acc[i][j] = fmaf(a[i], b[j], acc[i][j]);
        }
        __syncthreads();
    }

#pragma unroll
    for (int i = 0; i < 8; i++) {
        float* p = &Y[(size_t)(bm + ty * 8 + i) * DIM + bn + tx * 8];
        *reinterpret_cast<float4*>(p)     = *reinterpret_cast<float4*>(&acc[i][0]);
        *reinterpret_cast<float4*>(p + 4) = *reinterpret_cast<float4*>(&acc[i][4]);
    }
}

// ---------------- kernel 5: h = A@y, LeakyReLU, LayerNorm (fused) -----------
// One block per node row n; 512 threads cover all 8 batches.
// Thread t: batch b = t>>6, float4 channel chunk c = t&63 (covers 256 floats).
__global__ void __launch_bounds__(512) k_spmm_ln(const float* __restrict__ Y,
                                                 const float* __restrict__ gamma,
                                                 const float* __restrict__ beta,
                                                 float* __restrict__ out) {
    const int n    = blockIdx.x;
    const int tid  = threadIdx.x;
    const int b    = tid >> 6;        // 0..7
    const int c    = tid & 63;        // 0..63 -> floats [c*4, c*4+4)
    const int warp = tid >> 5;        // 0..15 ; batch b owns warps 2b, 2b+1
    const int lane = tid & 31;

    __shared__ int   cols_s[MAXDEG];
    __shared__ float red_s[16], red_q[16];

    const int deg = g_deg[n];
    if (tid < deg) cols_s[tid] = g_cols[n * MAXDEG + tid];
    const float4 g4  = __ldg(&reinterpret_cast<const float4*>(gamma)[c]);
    const float4 be4 = __ldg(&reinterpret_cast<const float4*>(beta)[c]);
    __syncthreads();

    const float4* Yb4 =
        reinterpret_cast<const float4*>(Y + (size_t)b * NROWS * DIM);

    float4 a0 = make_float4(0.f, 0.f, 0.f, 0.f);
    float4 a1 = make_float4(0.f, 0.f, 0.f, 0.f);
    float4 a2 = make_float4(0.f, 0.f, 0.f, 0.f);
    float4 a3 = make_float4(0.f, 0.f, 0.f, 0.f);
    int i = 0;
    for (; i + 4 <= deg; i += 4) {
        float4 v0 = __ldg(&Yb4[(size_t)cols_s[i]     * 64 + c]);
        float4 v1 = __ldg(&Yb4[(size_t)cols_s[i + 1] * 64 + c]);
        float4 v2 = __ldg(&Yb4[(size_t)cols_s[i + 2] * 64 + c]);
        float4 v3 = __ldg(&Yb4[(size_t)cols_s[i + 3] * 64 + c]);
        a0.x += v0.x; a0.y += v0.y; a0.z += v0.z; a0.w += v0.w;
        a1.x += v1.x; a1.y += v1.y; a1.z += v1.z; a1.w += v1.w;
        a2.x += v2.x; a2.y += v2.y; a2.z += v2.z; a2.w += v2.w;
        a3.x += v3.x; a3.y += v3.y; a3.z += v3.z; a3.w += v3.w;
    }
    for (; i < deg; i++) {
        float4 v0 = __ldg(&Yb4[(size_t)cols_s[i] * 64 + c]);
        a0.x += v0.x; a0.y += v0.y; a0.z += v0.z; a0.w += v0.w;
    }
    float4 v;
    v.x = (a0.x + a1.x) + (a2.x + a3.x);
    v.y = (a0.y + a1.y) + (a2.y + a3.y);
    v.z = (a0.z + a1.z) + (a2.z + a3.z);
    v.w = (a0.w + a1.w) + (a2.w + a3.w);

    // LeakyReLU(0.1)
    v.x = v.x >= 0.f ? v.x : 0.1f * v.x;
    v.y = v.y >= 0.f ? v.y : 0.1f * v.y;
    v.z = v.z >= 0.f ? v.z : 0.1f * v.z;
    v.w = v.w >= 0.f ? v.w : 0.1f * v.w;

    // LayerNorm over the 256 channels of (b, n): reduce over 64 threads (2 warps)
    float s = (v.x + v.y) + (v.z + v.w);
    float q = (v.x * v.x + v.y * v.y) + (v.z * v.z + v.w * v.w);
#pragma unroll
    for (int off = 16; off > 0; off >>= 1) {
        s += __shfl_down_sync(0xffffffffu, s, off);
        q += __shfl_down_sync(0xffffffffu, q, off);
    }
    if (lane == 0) { red_s[warp] = s; red_q[warp] = q; }
    __syncthreads();
    const float st = red_s[2 * b] + red_s[2 * b + 1];
    const float qt = red_q[2 * b] + red_q[2 * b + 1];

    const float mean = st * (1.f / 256.f);
    const float var  = qt * (1.f / 256.f) - mean * mean;
    const float inv  = rsqrtf(var + 1e-5f);

    float4 o;
    o.x = g4.x * (v.x - mean) * inv + be4.x;
    o.y = g4.y * (v.y - mean) * inv + be4.y;
    o.z = g4.z * (v.z - mean) * inv + be4.z;
    o.w = g4.w * (v.w - mean) * inv + be4.w;
    reinterpret_cast<float4*>(out)[((size_t)b * NROWS + n) * 64 + c] = o;
}

// ---------------- launcher ---------------------------------------------------
extern "C" void kernel_launch(void* const* d_in, const int* in_sizes, int n_in,
                              void* d_out, int out_size) {
    const float* x     = (const float*)d_in[0];   // (8, 8192, 256) f32
    const float* W     = (const float*)d_in[1];   // (256, 256) f32
    const float* gamma = (const float*)d_in[2];   // (256,) f32
    const float* beta  = (const float*)d_in[3];   // (256,) f32
    const void*  edges = d_in[4];                 // (262144, 2) int32 or int64
    const int ne = in_sizes[4] / 2;               // 262144 pairs either way
    float* out = (float*)d_out;

    k_clear<<<2048, 256>>>();
    k_detect<<<1, 256>>>((const int*)edges);
    k_scatter<<<(ne + 255) / 256, 256>>>(edges, ne);
    k_csr<<<NROWS / 8, 256>>>();
    dim3 ggrid(DIM / 128, (BATCH * NROWS) / 128);     // (2, 512)
    k_gemm<<<ggrid, 256>>>(x, W, g_y);
    k_spmm_ln<<<NROWS, 512>>>(g_y, gamma, beta, out);
}